// round 15
// baseline (speedup 1.0000x reference)
#include <cuda_runtime.h>

#define NB   2
#define NK   8
#define NPAIR 4            // (n, k-pair) channels: pair = n*2 + k/2
#define VOX  512000
#define B1   128
#define CHUNK 4000

typedef unsigned long long u64;

// ---------------- packed f32x2 helpers ----------------
__device__ __forceinline__ u64 pack2(float lo, float hi) {
    u64 r; asm("mov.b64 %0,{%1,%2};" : "=l"(r) : "f"(lo), "f"(hi)); return r;
}
__device__ __forceinline__ float2 unpack2(u64 p) {
    float2 f; asm("mov.b64 {%0,%1},%2;" : "=f"(f.x), "=f"(f.y) : "l"(p)); return f;
}
__device__ __forceinline__ void fma2(u64 &a, u64 v, u64 c) {
    asm("fma.rn.f32x2 %0,%1,%2,%0;" : "+l"(a) : "l"(v), "l"(c));
}

// 11-tap unnormalized Gaussian, sigma=4: g[t] = exp(-(t-5)^2/32), symmetric
__device__ __forceinline__ void mk_taps(u64* t) {
    const float g[6] = { 0.45783335f, 0.60653066f, 0.75483960f,
                         0.88249690f, 0.96923321f, 1.00000000f };
    #pragma unroll
    for (int i = 0; i < 6; i++) t[i] = pack2(g[i], g[i]);
}

// Sliding-window 11-tap conv: L outputs, L+10 inputs, ring of 11 accumulators.
template<int L, typename LoadF, typename EmitF>
__device__ __forceinline__ void slide11(const u64* taps, LoadF&& load, EmitF&& emit) {
    u64 acc[11];
    #pragma unroll
    for (int s = 0; s < 11; s++) acc[s] = 0ull;
    #pragma unroll
    for (int i = 0; i < L + 10; i++) {
        u64 v = load(i);
        #pragma unroll
        for (int j = 0; j <= 10; j++) {
            int o = i - 10 + j;
            if (o >= 0 && o < L) {
                int t = 10 - j;
                int u = (t <= 5) ? t : 10 - t;
                fma2(acc[o % 11], v, taps[u]);
            }
        }
        if (i >= 10) {
            emit(i - 10, acc[(i - 10) % 11]);
            acc[(i - 10) % 11] = 0ull;
        }
    }
}

// Software-pipelined variant: PF loads in flight before the first consume.
template<int L, int PF, typename LoadF, typename EmitF>
__device__ __forceinline__ void slide11p(const u64* taps, LoadF&& load, EmitF&& emit) {
    u64 acc[11];
    #pragma unroll
    for (int s = 0; s < 11; s++) acc[s] = 0ull;
    u64 buf[PF];
    #pragma unroll
    for (int p = 0; p < PF; p++) buf[p] = load(p);
    #pragma unroll
    for (int i = 0; i < L + 10; i++) {
        u64 v = buf[i % PF];
        if (i + PF < L + 10) buf[i % PF] = load(i + PF);
        #pragma unroll
        for (int j = 0; j <= 10; j++) {
            int o = i - 10 + j;
            if (o >= 0 && o < L) {
                int t = 10 - j;
                int u = (t <= 5) ? t : 10 - t;
                fma2(acc[o % 11], v, taps[u]);
            }
        }
        if (i >= 10) {
            emit(i - 10, acc[(i - 10) % 11]);
            acc[(i - 10) % 11] = 0ull;
        }
    }
}

// ---------------- scratch ----------------
__device__ float  g_part1[NB * B1 * 8];
__device__ float  g_mean[NK];
__device__ u64    g_bufA[NPAIR * VOX];    // conv-W(labels) for k-pairs, [pair][h][w][d]
__device__ float4 g_partC[NPAIR * 80];    // per (pair,w): (num0,den0,num1,den1)

// ---------------- K1: partial sums for class means (float4 streams) ----------------
__global__ __launch_bounds__(256) void k_sums(const float* __restrict__ labels,
                                              const float* __restrict__ inputs) {
    int n = blockIdx.y, b = blockIdx.x;
    int j0 = b * (CHUNK / 4);
    float a[8];
    #pragma unroll
    for (int j = 0; j < 8; j++) a[j] = 0.f;
    const float4* ip4 = (const float4*)(inputs + (size_t)n * VOX);
    for (int j = j0 + threadIdx.x; j < j0 + CHUNK / 4; j += blockDim.x) {
        float4 iv = __ldg(ip4 + j);
        #pragma unroll
        for (int k = 0; k < 4; k++) {
            const float4* lp4 = (const float4*)(labels + (size_t)(n * 4 + k) * VOX);
            float4 lv = __ldg(lp4 + j);
            a[k]     += (lv.x + lv.y) + (lv.z + lv.w);
            a[4 + k] += (iv.x * lv.x + iv.y * lv.y) + (iv.z * lv.z + iv.w * lv.w);
        }
    }
    #pragma unroll
    for (int o = 16; o > 0; o >>= 1)
        #pragma unroll
        for (int j = 0; j < 8; j++)
            a[j] += __shfl_down_sync(0xffffffffu, a[j], o);
    __shared__ float s[8][8];
    int wid = threadIdx.x >> 5, lid = threadIdx.x & 31;
    if (lid == 0)
        #pragma unroll
        for (int j = 0; j < 8; j++) s[wid][j] = a[j];
    __syncthreads();
    if (threadIdx.x < 8) {
        int j = threadIdx.x;
        float acc = 0.f;
        #pragma unroll
        for (int w = 0; w < 8; w++) acc += s[w][j];
        g_part1[(size_t)(n * B1 + b) * 8 + j] = acc;
    }
}

// ---------------- K2: finish means ----------------
__global__ __launch_bounds__(256) void k_means() {
    int wid = threadIdx.x >> 5, lid = threadIdx.x & 31;   // wid = nk
    int n = wid >> 2, k = wid & 3;
    float sp = 0.f, sip = 0.f;
    for (int b = lid; b < B1; b += 32) {
        const float* p = g_part1 + (size_t)(n * B1 + b) * 8;
        sp  += p[k];
        sip += p[4 + k];
    }
    #pragma unroll
    for (int o = 16; o > 0; o >>= 1) {
        sp  += __shfl_down_sync(0xffffffffu, sp, o);
        sip += __shfl_down_sync(0xffffffffu, sip, o);
    }
    if (lid == 0) g_mean[wid] = sip / (sp + 5.12f);   // 1e-5 * 512000
}

// ---------------- KA: conv-W of labels, k-pairs packed ----------------
// grid = NPAIR*80 (pair,h); 240 active threads = 80 d-lanes x 3 w-segments
__global__ __launch_bounds__(256) void kA(const float* __restrict__ labels) {
    int bx = blockIdx.x;
    int pair = bx / 80, h = bx % 80;
    int n = pair >> 1, k0 = (pair & 1) * 2;
    int tid = threadIdx.x;
    if (tid >= 240) return;
    int d = tid % 80, seg = tid / 80;
    u64 taps[6]; mk_taps(taps);
    const float* lp0 = labels + (size_t)(n * 4 + k0)     * VOX + (size_t)h * 6400 + d;
    const float* lp1 = labels + (size_t)(n * 4 + k0 + 1) * VOX + (size_t)h * 6400 + d;
    u64*         op  = g_bufA + (size_t)pair * VOX + (size_t)h * 6400 + d;
    int w0 = seg * 27;
    auto load = [&](int i) -> u64 {
        int w = w0 - 5 + i;
        if (w < 0 || w >= 80) return 0ull;
        return pack2(__ldg(lp0 + w * 80), __ldg(lp1 + w * 80));
    };
    auto emit = [&](int o, u64 a) { op[(w0 + o) * 80] = a; };
    if (seg < 2) slide11<27>(taps, load, emit);
    else         slide11<26>(taps, load, emit);
}

// ---------------- KB: conv-H + conv-D of C + fused epilogue ----------------
// grid = NPAIR*80 (pair,w). Per chunk: stage1 conv-H bufA->spk (u64 pairs),
// stage labels(2ch)+inputs, stage2 conv-D + epilogue:
//   den_k += w_k*C_k,  num_k += lab_k*w_k*C_k,  w_k = exp(-((inp-mean_k)^2)^2)
__global__ __launch_bounds__(256) void kB(const float* __restrict__ labels,
                                          const float* __restrict__ inputs) {
    extern __shared__ char smemraw[];
    u64*   spk   = (u64*)smemraw;                       // 80 x 51 (u64)
    float* slab0 = (float*)(smemraw + 80 * 51 * 8);     // 80 x 41
    float* slab1 = slab0 + 80 * 41;
    float* sinp  = slab1 + 80 * 41;

    int bx = blockIdx.x;
    int pair = bx / 80, w = bx % 80;
    int n = pair >> 1, k0 = (pair & 1) * 2;
    int nk0 = n * 4 + k0;
    int tid = threadIdx.x;

    float m0 = g_mean[nk0], m1 = g_mean[nk0 + 1];

    u64 taps[6]; mk_taps(taps);
    float num0 = 0.f, den0 = 0.f, num1 = 0.f, den1 = 0.f;

    const u64*   base  = g_bufA + (size_t)pair * VOX + (size_t)w * 80;
    const float* lb0   = labels + (size_t)nk0 * VOX + (size_t)w * 80;
    const float* lb1   = lb0 + VOX;
    const float* ib    = inputs + (size_t)n * VOX + (size_t)w * 80;

    for (int chunk = 0; chunk < 2; chunk++) {
        int cstart = chunk * 40;       // output d range [cstart, cstart+40)
        // zero pad cols: chunk0 -> j in [0,5) (d<0); chunk1 -> j in [45,50) (d>=80)
        for (int idx = tid; idx < 80 * 5; idx += 256) {
            int r = idx / 5, p = idx % 5;
            int j = (chunk == 0) ? p : 45 + p;
            spk[r * 51 + j] = 0ull;
        }
        // stage1: conv along H into smem; 225 threads = 45 d-cols x 5 h-segments of 16
        if (tid < 225) {
            int jv = tid % 45, hseg = tid / 45;
            int j  = (chunk == 0) ? jv + 5 : jv;      // smem col
            int dg = (chunk == 0) ? jv     : 35 + jv; // global d
            int h0 = hseg * 16;
            const u64* cp = base + dg;
            auto load = [&](int i) -> u64 {
                int hh = h0 - 5 + i;
                return (hh < 0 || hh >= 80) ? 0ull : __ldg(cp + (size_t)hh * 6400);
            };
            auto emit = [&](int o, u64 a) { spk[(h0 + o) * 51 + j] = a; };
            slide11p<16, 6>(taps, load, emit);
        }
        // stage labels (both k) + inputs, coalesced along d
        for (int idx = tid; idx < 80 * 40; idx += 256) {
            int r = idx / 40, dl = idx % 40;
            size_t g = (size_t)r * 6400 + cstart + dl;
            int s = r * 41 + dl;
            slab0[s] = __ldg(lb0 + g);
            slab1[s] = __ldg(lb1 + g);
            sinp[s]  = __ldg(ib  + g);
        }
        __syncthreads();
        // stage2: conv along D over spk + epilogue; 240 threads = 80 rows x 3 d-segs
        if (tid < 240) {
            int r = tid % 80, dseg = tid / 80;
            int d0 = dseg * 14;
            auto load = [&](int i) -> u64 { return spk[r * 51 + d0 + i]; };
            auto emit = [&](int o, u64 a) {
                float2 c = unpack2(a);
                int s = r * 41 + d0 + o;
                float iv = sinp[s];
                float t0 = iv - m0; float q0 = t0 * t0; q0 *= q0;
                float t1 = iv - m1; float q1 = t1 * t1; q1 *= q1;
                float w0 = __expf(-q0);
                float w1 = __expf(-q1);
                float wc0 = w0 * c.x, wc1 = w1 * c.y;
                den0 += wc0; num0 += slab0[s] * wc0;
                den1 += wc1; num1 += slab1[s] * wc1;
            };
            if (dseg < 2) slide11<14>(taps, load, emit);
            else          slide11<12>(taps, load, emit);
        }
        __syncthreads();
    }

    // block reduce 4 accumulators
    #pragma unroll
    for (int o = 16; o > 0; o >>= 1) {
        num0 += __shfl_down_sync(0xffffffffu, num0, o);
        den0 += __shfl_down_sync(0xffffffffu, den0, o);
        num1 += __shfl_down_sync(0xffffffffu, num1, o);
        den1 += __shfl_down_sync(0xffffffffu, den1, o);
    }
    __shared__ float4 sacc[8];
    int wid = tid >> 5, lid = tid & 31;
    if (lid == 0) sacc[wid] = make_float4(num0, den0, num1, den1);
    __syncthreads();
    if (tid == 0) {
        float4 t = make_float4(0.f, 0.f, 0.f, 0.f);
        #pragma unroll
        for (int j = 0; j < 8; j++) {
            t.x += sacc[j].x; t.y += sacc[j].y;
            t.z += sacc[j].z; t.w += sacc[j].w;
        }
        g_partC[bx] = t;
    }
}

// ---------------- K final: ratio / loss ----------------
__global__ __launch_bounds__(256) void k_final(float* __restrict__ out) {
    int wid = threadIdx.x >> 5, lid = threadIdx.x & 31;   // wid = nk
    int n = wid >> 2, k = wid & 3;
    int pair = n * 2 + (k >> 1);
    int sel  = k & 1;
    __shared__ float sr[8];
    {
        float num = 0.f, den = 0.f;
        for (int j = lid; j < 80; j += 32) {
            float4 p = g_partC[pair * 80 + j];
            num += sel ? p.z : p.x;
            den += sel ? p.w : p.y;
        }
        #pragma unroll
        for (int o = 16; o > 0; o >>= 1) {
            num += __shfl_down_sync(0xffffffffu, num, o);
            den += __shfl_down_sync(0xffffffffu, den, o);
        }
        if (lid == 0) sr[wid] = fabsf(num / (den + 1e-6f));
    }
    __syncthreads();
    if (threadIdx.x == 0) {
        float loss = 0.f;
        #pragma unroll
        for (int k2 = 0; k2 < 4; k2++)
            loss += 0.5f * (sr[k2] + sr[4 + k2]);
        out[0] = 4.0f - loss;
    }
}

extern "C" void kernel_launch(void* const* d_in, const int* in_sizes, int n_in,
                              void* d_out, int out_size) {
    const float* labels = (const float*)d_in[0];
    const float* inputs = (const float*)d_in[1];
    if (n_in >= 2 && in_sizes[0] < in_sizes[1]) {
        const float* t = labels; labels = inputs; inputs = t;
    }
    float* out = (float*)d_out;

    const int KB_SMEM = 80 * 51 * 8 + 3 * 80 * 41 * 4;   // 72,000 B
    cudaFuncSetAttribute(kB, cudaFuncAttributeMaxDynamicSharedMemorySize, KB_SMEM);

    k_sums <<<dim3(B1, NB), 256>>>(labels, inputs);
    k_means<<<1, 256>>>();
    kA     <<<NPAIR * 80, 256>>>(labels);
    kB     <<<NPAIR * 80, 256, KB_SMEM>>>(labels, inputs);
    k_final<<<1, 256>>>(out);
}

// round 16
// speedup vs baseline: 1.4482x; 1.4482x over previous
#include <cuda_runtime.h>

#define NB   2
#define NK   8
#define NPAIR 4            // (n, k-pair) channels: pair = n*2 + k/2
#define VOX  512000
#define B1   128
#define CHUNK 4000

typedef unsigned long long u64;

// ---------------- packed f32x2 helpers ----------------
__device__ __forceinline__ u64 pack2(float lo, float hi) {
    u64 r; asm("mov.b64 %0,{%1,%2};" : "=l"(r) : "f"(lo), "f"(hi)); return r;
}
__device__ __forceinline__ float2 unpack2(u64 p) {
    float2 f; asm("mov.b64 {%0,%1},%2;" : "=f"(f.x), "=f"(f.y) : "l"(p)); return f;
}
__device__ __forceinline__ void fma2(u64 &a, u64 v, u64 c) {
    asm("fma.rn.f32x2 %0,%1,%2,%0;" : "+l"(a) : "l"(v), "l"(c));
}

// 11-tap unnormalized Gaussian, sigma=4: g[t] = exp(-(t-5)^2/32), symmetric
__device__ __forceinline__ void mk_taps(u64* t) {
    const float g[6] = { 0.45783335f, 0.60653066f, 0.75483960f,
                         0.88249690f, 0.96923321f, 1.00000000f };
    #pragma unroll
    for (int i = 0; i < 6; i++) t[i] = pack2(g[i], g[i]);
}

// Sliding-window 11-tap conv: L outputs, L+10 inputs, ring of 11 accumulators.
template<int L, typename LoadF, typename EmitF>
__device__ __forceinline__ void slide11(const u64* taps, LoadF&& load, EmitF&& emit) {
    u64 acc[11];
    #pragma unroll
    for (int s = 0; s < 11; s++) acc[s] = 0ull;
    #pragma unroll
    for (int i = 0; i < L + 10; i++) {
        u64 v = load(i);
        #pragma unroll
        for (int j = 0; j <= 10; j++) {
            int o = i - 10 + j;
            if (o >= 0 && o < L) {
                int t = 10 - j;
                int u = (t <= 5) ? t : 10 - t;
                fma2(acc[o % 11], v, taps[u]);
            }
        }
        if (i >= 10) {
            emit(i - 10, acc[(i - 10) % 11]);
            acc[(i - 10) % 11] = 0ull;
        }
    }
}

// Software-pipelined variant: PF loads in flight before the first consume.
template<int L, int PF, typename LoadF, typename EmitF>
__device__ __forceinline__ void slide11p(const u64* taps, LoadF&& load, EmitF&& emit) {
    u64 acc[11];
    #pragma unroll
    for (int s = 0; s < 11; s++) acc[s] = 0ull;
    u64 buf[PF];
    #pragma unroll
    for (int p = 0; p < PF; p++) buf[p] = load(p);
    #pragma unroll
    for (int i = 0; i < L + 10; i++) {
        u64 v = buf[i % PF];
        if (i + PF < L + 10) buf[i % PF] = load(i + PF);
        #pragma unroll
        for (int j = 0; j <= 10; j++) {
            int o = i - 10 + j;
            if (o >= 0 && o < L) {
                int t = 10 - j;
                int u = (t <= 5) ? t : 10 - t;
                fma2(acc[o % 11], v, taps[u]);
            }
        }
        if (i >= 10) {
            emit(i - 10, acc[(i - 10) % 11]);
            acc[(i - 10) % 11] = 0ull;
        }
    }
}

// ---------------- scratch ----------------
__device__ float  g_part1[NB * B1 * 8];
__device__ float  g_mean[NK];
__device__ u64    g_bufA[NPAIR * VOX];      // conv-W(labels) k-pairs, [pair][h][w][d]
__device__ float4 g_partC[NPAIR * 80 * 2];  // per (pair,w,half): (num0,den0,num1,den1)

// ---------------- K1: partial sums for class means (float4 streams) ----------------
__global__ __launch_bounds__(256) void k_sums(const float* __restrict__ labels,
                                              const float* __restrict__ inputs) {
    int n = blockIdx.y, b = blockIdx.x;
    int j0 = b * (CHUNK / 4);
    float a[8];
    #pragma unroll
    for (int j = 0; j < 8; j++) a[j] = 0.f;
    const float4* ip4 = (const float4*)(inputs + (size_t)n * VOX);
    for (int j = j0 + threadIdx.x; j < j0 + CHUNK / 4; j += blockDim.x) {
        float4 iv = __ldg(ip4 + j);
        #pragma unroll
        for (int k = 0; k < 4; k++) {
            const float4* lp4 = (const float4*)(labels + (size_t)(n * 4 + k) * VOX);
            float4 lv = __ldg(lp4 + j);
            a[k]     += (lv.x + lv.y) + (lv.z + lv.w);
            a[4 + k] += (iv.x * lv.x + iv.y * lv.y) + (iv.z * lv.z + iv.w * lv.w);
        }
    }
    #pragma unroll
    for (int o = 16; o > 0; o >>= 1)
        #pragma unroll
        for (int j = 0; j < 8; j++)
            a[j] += __shfl_down_sync(0xffffffffu, a[j], o);
    __shared__ float s[8][8];
    int wid = threadIdx.x >> 5, lid = threadIdx.x & 31;
    if (lid == 0)
        #pragma unroll
        for (int j = 0; j < 8; j++) s[wid][j] = a[j];
    __syncthreads();
    if (threadIdx.x < 8) {
        int j = threadIdx.x;
        float acc = 0.f;
        #pragma unroll
        for (int w = 0; w < 8; w++) acc += s[w][j];
        g_part1[(size_t)(n * B1 + b) * 8 + j] = acc;
    }
}

// ---------------- K2: finish means ----------------
__global__ __launch_bounds__(256) void k_means() {
    int wid = threadIdx.x >> 5, lid = threadIdx.x & 31;   // wid = nk
    int n = wid >> 2, k = wid & 3;
    float sp = 0.f, sip = 0.f;
    for (int b = lid; b < B1; b += 32) {
        const float* p = g_part1 + (size_t)(n * B1 + b) * 8;
        sp  += p[k];
        sip += p[4 + k];
    }
    #pragma unroll
    for (int o = 16; o > 0; o >>= 1) {
        sp  += __shfl_down_sync(0xffffffffu, sp, o);
        sip += __shfl_down_sync(0xffffffffu, sip, o);
    }
    if (lid == 0) g_mean[wid] = sip / (sp + 5.12f);   // 1e-5 * 512000
}

// ---------------- KA: conv-W of labels, k-pairs packed ----------------
// grid = NPAIR*80 (pair,h); 240 active threads = 80 d-lanes x 3 w-segments
__global__ __launch_bounds__(256) void kA(const float* __restrict__ labels) {
    int bx = blockIdx.x;
    int pair = bx / 80, h = bx % 80;
    int n = pair >> 1, k0 = (pair & 1) * 2;
    int tid = threadIdx.x;
    if (tid >= 240) return;
    int d = tid % 80, seg = tid / 80;
    u64 taps[6]; mk_taps(taps);
    const float* lp0 = labels + (size_t)(n * 4 + k0)     * VOX + (size_t)h * 6400 + d;
    const float* lp1 = labels + (size_t)(n * 4 + k0 + 1) * VOX + (size_t)h * 6400 + d;
    u64*         op  = g_bufA + (size_t)pair * VOX + (size_t)h * 6400 + d;
    int w0 = seg * 27;
    auto load = [&](int i) -> u64 {
        int w = w0 - 5 + i;
        if (w < 0 || w >= 80) return 0ull;
        return pack2(__ldg(lp0 + w * 80), __ldg(lp1 + w * 80));
    };
    auto emit = [&](int o, u64 a) { op[(w0 + o) * 80] = a; };
    if (seg < 2) slide11<27>(taps, load, emit);
    else         slide11<26>(taps, load, emit);
}

// ---------------- KB: conv-H + conv-D of C + fused epilogue ----------------
// grid = NPAIR*80*2: block = (pair, w, h-half of 40 rows). 2 d-chunks in-block.
// Epilogue: w_k = exp(-((inp-mean_k)^2)^2); den_k += w_k*C_k; num_k += lab_k*w_k*C_k
__global__ __launch_bounds__(256) void kB(const float* __restrict__ labels,
                                          const float* __restrict__ inputs) {
    __shared__ u64   spk[40 * 51];     // conv-H result (pair-packed); 40 rows x 50 cols
    __shared__ u64   slabp[40 * 41];   // labels pair-packed (stride 41, odd)
    __shared__ float sinp[40 * 41];    // inputs (stride 41, odd)

    int bx = blockIdx.x;
    int half = bx & 1;
    int pwi  = bx >> 1;
    int pair = pwi / 80, w = pwi % 80;
    int n = pair >> 1, k0 = (pair & 1) * 2;
    int nk0 = n * 4 + k0;
    int h0 = half * 40;
    int tid = threadIdx.x;

    float m0 = g_mean[nk0], m1 = g_mean[nk0 + 1];

    u64 taps[6]; mk_taps(taps);
    float num0 = 0.f, den0 = 0.f, num1 = 0.f, den1 = 0.f;

    const u64*   base = g_bufA + (size_t)pair * VOX + (size_t)w * 80;
    const float* lb0  = labels + (size_t)nk0 * VOX + (size_t)w * 80;
    const float* lb1  = lb0 + VOX;
    const float* ib   = inputs + (size_t)n * VOX + (size_t)w * 80;

    for (int chunk = 0; chunk < 2; chunk++) {
        int cstart = chunk * 40;       // output d range [cstart, cstart+40)
        // zero pad cols: chunk0 -> j in [0,5) (d<0); chunk1 -> j in [45,50) (d>=80)
        for (int idx = tid; idx < 40 * 5; idx += 256) {
            int r = idx / 5, p = idx % 5;
            int j = (chunk == 0) ? p : 45 + p;
            spk[r * 51 + j] = 0ull;
        }
        // stage1: conv along H into smem; 225 threads = 45 d-cols x 5 h-segments of 8
        if (tid < 225) {
            int jv = tid % 45, hseg = tid / 45;
            int j  = (chunk == 0) ? jv + 5 : jv;      // smem col
            int dg = (chunk == 0) ? jv     : 35 + jv; // global d
            int r0 = hseg * 8;                        // local row start
            const u64* cp = base + dg;
            auto load = [&](int i) -> u64 {
                int hh = h0 + r0 - 5 + i;
                return (hh < 0 || hh >= 80) ? 0ull : __ldg(cp + (size_t)hh * 6400);
            };
            auto emit = [&](int o, u64 a) { spk[(r0 + o) * 51 + j] = a; };
            slide11p<8, 6>(taps, load, emit);
        }
        // stage labels (pair-packed) + inputs, coalesced along d
        for (int idx = tid; idx < 40 * 40; idx += 256) {
            int r = idx / 40, dl = idx % 40;
            size_t g = (size_t)(h0 + r) * 6400 + cstart + dl;
            int s = r * 41 + dl;
            slabp[s] = pack2(__ldg(lb0 + g), __ldg(lb1 + g));
            sinp[s]  = __ldg(ib + g);
        }
        __syncthreads();
        // stage2: conv along D over spk + epilogue; 240 threads = 40 rows x 6 d-segs
        if (tid < 240) {
            int r = tid % 40, dseg = tid / 40;
            int d0 = (dseg < 4) ? dseg * 7 : 28 + (dseg - 4) * 6;
            auto load = [&](int i) -> u64 { return spk[r * 51 + d0 + i]; };
            auto emit = [&](int o, u64 a) {
                float2 c = unpack2(a);
                int s = r * 41 + d0 + o;
                float iv = sinp[s];
                float2 lv = unpack2(slabp[s]);
                float t0 = iv - m0; float q0 = t0 * t0; q0 *= q0;
                float t1 = iv - m1; float q1 = t1 * t1; q1 *= q1;
                float w0 = __expf(-q0);
                float w1 = __expf(-q1);
                float wc0 = w0 * c.x, wc1 = w1 * c.y;
                den0 += wc0; num0 += lv.x * wc0;
                den1 += wc1; num1 += lv.y * wc1;
            };
            if (dseg < 4) slide11<7>(taps, load, emit);
            else          slide11<6>(taps, load, emit);
        }
        __syncthreads();
    }

    // block reduce 4 accumulators
    #pragma unroll
    for (int o = 16; o > 0; o >>= 1) {
        num0 += __shfl_down_sync(0xffffffffu, num0, o);
        den0 += __shfl_down_sync(0xffffffffu, den0, o);
        num1 += __shfl_down_sync(0xffffffffu, num1, o);
        den1 += __shfl_down_sync(0xffffffffu, den1, o);
    }
    __shared__ float4 sacc[8];
    int wid = tid >> 5, lid = tid & 31;
    if (lid == 0) sacc[wid] = make_float4(num0, den0, num1, den1);
    __syncthreads();
    if (tid == 0) {
        float4 t = make_float4(0.f, 0.f, 0.f, 0.f);
        #pragma unroll
        for (int j = 0; j < 8; j++) {
            t.x += sacc[j].x; t.y += sacc[j].y;
            t.z += sacc[j].z; t.w += sacc[j].w;
        }
        g_partC[bx] = t;
    }
}

// ---------------- K final: ratio / loss ----------------
__global__ __launch_bounds__(256) void k_final(float* __restrict__ out) {
    int wid = threadIdx.x >> 5, lid = threadIdx.x & 31;   // wid = nk
    int n = wid >> 2, k = wid & 3;
    int pair = n * 2 + (k >> 1);
    int sel  = k & 1;
    __shared__ float sr[8];
    {
        float num = 0.f, den = 0.f;
        for (int j = lid; j < 160; j += 32) {
            float4 p = g_partC[pair * 160 + j];
            num += sel ? p.z : p.x;
            den += sel ? p.w : p.y;
        }
        #pragma unroll
        for (int o = 16; o > 0; o >>= 1) {
            num += __shfl_down_sync(0xffffffffu, num, o);
            den += __shfl_down_sync(0xffffffffu, den, o);
        }
        if (lid == 0) sr[wid] = fabsf(num / (den + 1e-6f));
    }
    __syncthreads();
    if (threadIdx.x == 0) {
        float loss = 0.f;
        #pragma unroll
        for (int k2 = 0; k2 < 4; k2++)
            loss += 0.5f * (sr[k2] + sr[4 + k2]);
        out[0] = 4.0f - loss;
    }
}

extern "C" void kernel_launch(void* const* d_in, const int* in_sizes, int n_in,
                              void* d_out, int out_size) {
    const float* labels = (const float*)d_in[0];
    const float* inputs = (const float*)d_in[1];
    if (n_in >= 2 && in_sizes[0] < in_sizes[1]) {
        const float* t = labels; labels = inputs; inputs = t;
    }
    float* out = (float*)d_out;

    k_sums <<<dim3(B1, NB), 256>>>(labels, inputs);
    k_means<<<1, 256>>>();
    kA     <<<NPAIR * 80, 256>>>(labels);
    kB     <<<NPAIR * 80 * 2, 256>>>(labels, inputs);
    k_final<<<1, 256>>>(out);
}

// round 17
// speedup vs baseline: 1.4496x; 1.0010x over previous
#include <cuda_runtime.h>

#define NB   2
#define NK   8
#define NPAIR 4            // (n, k-pair) channels: pair = n*2 + k/2
#define VOX  512000

typedef unsigned long long u64;

// ---------------- packed f32x2 helpers ----------------
__device__ __forceinline__ u64 pack2(float lo, float hi) {
    u64 r; asm("mov.b64 %0,{%1,%2};" : "=l"(r) : "f"(lo), "f"(hi)); return r;
}
__device__ __forceinline__ float2 unpack2(u64 p) {
    float2 f; asm("mov.b64 {%0,%1},%2;" : "=f"(f.x), "=f"(f.y) : "l"(p)); return f;
}
__device__ __forceinline__ void fma2(u64 &a, u64 v, u64 c) {
    asm("fma.rn.f32x2 %0,%1,%2,%0;" : "+l"(a) : "l"(v), "l"(c));
}

// 11-tap unnormalized Gaussian, sigma=4: g[t] = exp(-(t-5)^2/32), symmetric
__device__ __forceinline__ void mk_taps(u64* t) {
    const float g[6] = { 0.45783335f, 0.60653066f, 0.75483960f,
                         0.88249690f, 0.96923321f, 1.00000000f };
    #pragma unroll
    for (int i = 0; i < 6; i++) t[i] = pack2(g[i], g[i]);
}

// Sliding-window 11-tap conv: L outputs, L+10 inputs, ring of 11 accumulators.
template<int L, typename LoadF, typename EmitF>
__device__ __forceinline__ void slide11(const u64* taps, LoadF&& load, EmitF&& emit) {
    u64 acc[11];
    #pragma unroll
    for (int s = 0; s < 11; s++) acc[s] = 0ull;
    #pragma unroll
    for (int i = 0; i < L + 10; i++) {
        u64 v = load(i);
        #pragma unroll
        for (int j = 0; j <= 10; j++) {
            int o = i - 10 + j;
            if (o >= 0 && o < L) {
                int t = 10 - j;
                int u = (t <= 5) ? t : 10 - t;
                fma2(acc[o % 11], v, taps[u]);
            }
        }
        if (i >= 10) {
            emit(i - 10, acc[(i - 10) % 11]);
            acc[(i - 10) % 11] = 0ull;
        }
    }
}

// Software-pipelined variant: PF loads in flight before the first consume.
template<int L, int PF, typename LoadF, typename EmitF>
__device__ __forceinline__ void slide11p(const u64* taps, LoadF&& load, EmitF&& emit) {
    u64 acc[11];
    #pragma unroll
    for (int s = 0; s < 11; s++) acc[s] = 0ull;
    u64 buf[PF];
    #pragma unroll
    for (int p = 0; p < PF; p++) buf[p] = load(p);
    #pragma unroll
    for (int i = 0; i < L + 10; i++) {
        u64 v = buf[i % PF];
        if (i + PF < L + 10) buf[i % PF] = load(i + PF);
        #pragma unroll
        for (int j = 0; j <= 10; j++) {
            int o = i - 10 + j;
            if (o >= 0 && o < L) {
                int t = 10 - j;
                int u = (t <= 5) ? t : 10 - t;
                fma2(acc[o % 11], v, taps[u]);
            }
        }
        if (i >= 10) {
            emit(i - 10, acc[(i - 10) % 11]);
            acc[(i - 10) % 11] = 0ull;
        }
    }
}

// ---------------- scratch ----------------
__device__ u64    g_bufA[NPAIR * VOX];      // conv-W(labels) k-pairs, [pair][h][w][d]
__device__ float4 g_part2[NPAIR * 80];      // per (pair,h): (sum_l0, sum_il0, sum_l1, sum_il1)
__device__ float4 g_partC[NPAIR * 80 * 2];  // per (pair,w,half): (num0,den0,num1,den1)

// ---------------- K1': fused plane sums + conv-W of labels (k-pairs packed) -------
// grid = NPAIR*80 (pair,h), 256 threads.
__global__ __launch_bounds__(256) void kAB(const float* __restrict__ labels,
                                           const float* __restrict__ inputs) {
    int bx = blockIdx.x;
    int pair = bx / 80, h = bx % 80;
    int n = pair >> 1, k0 = (pair & 1) * 2;
    int tid = threadIdx.x;

    const float* lp0 = labels + (size_t)(n * 4 + k0)     * VOX + (size_t)h * 6400;
    const float* lp1 = labels + (size_t)(n * 4 + k0 + 1) * VOX + (size_t)h * 6400;
    const float* ip  = inputs + (size_t)n * VOX + (size_t)h * 6400;

    // (a) plane partial sums (coalesced float4)
    {
        float s0 = 0.f, si0 = 0.f, s1 = 0.f, si1 = 0.f;
        const float4* l04 = (const float4*)lp0;
        const float4* l14 = (const float4*)lp1;
        const float4* i4  = (const float4*)ip;
        for (int j = tid; j < 1600; j += 256) {
            float4 a = __ldg(l04 + j);
            float4 b = __ldg(l14 + j);
            float4 c = __ldg(i4  + j);
            s0  += (a.x + a.y) + (a.z + a.w);
            s1  += (b.x + b.y) + (b.z + b.w);
            si0 += (a.x * c.x + a.y * c.y) + (a.z * c.z + a.w * c.w);
            si1 += (b.x * c.x + b.y * c.y) + (b.z * c.z + b.w * c.w);
        }
        #pragma unroll
        for (int o = 16; o > 0; o >>= 1) {
            s0  += __shfl_down_sync(0xffffffffu, s0, o);
            si0 += __shfl_down_sync(0xffffffffu, si0, o);
            s1  += __shfl_down_sync(0xffffffffu, s1, o);
            si1 += __shfl_down_sync(0xffffffffu, si1, o);
        }
        __shared__ float4 sacc[8];
        int wid = tid >> 5, lid = tid & 31;
        if (lid == 0) sacc[wid] = make_float4(s0, si0, s1, si1);
        __syncthreads();
        if (tid == 0) {
            float4 t = make_float4(0.f, 0.f, 0.f, 0.f);
            #pragma unroll
            for (int j = 0; j < 8; j++) {
                t.x += sacc[j].x; t.y += sacc[j].y;
                t.z += sacc[j].z; t.w += sacc[j].w;
            }
            g_part2[bx] = t;
        }
    }

    // (b) conv along W (kA-exact); 240 active threads = 80 d-lanes x 3 w-segments
    if (tid >= 240) return;
    int d = tid % 80, seg = tid / 80;
    u64 taps[6]; mk_taps(taps);
    const float* lq0 = lp0 + d;
    const float* lq1 = lp1 + d;
    u64*         op  = g_bufA + (size_t)pair * VOX + (size_t)h * 6400 + d;
    int w0 = seg * 27;
    auto load = [&](int i) -> u64 {
        int w = w0 - 5 + i;
        if (w < 0 || w >= 80) return 0ull;
        return pack2(__ldg(lq0 + w * 80), __ldg(lq1 + w * 80));
    };
    auto emit = [&](int o, u64 a) { op[(w0 + o) * 80] = a; };
    if (seg < 2) slide11<27>(taps, load, emit);
    else         slide11<26>(taps, load, emit);
}

// ---------------- KB: conv-H + conv-D of C + fused epilogue (+ means prologue) ----
// grid = NPAIR*80*2: block = (pair, w, h-half of 40 rows). 2 d-chunks in-block.
__global__ __launch_bounds__(256) void kB(const float* __restrict__ labels,
                                          const float* __restrict__ inputs) {
    __shared__ u64   spk[40 * 51];     // conv-H result (pair-packed)
    __shared__ u64   slabp[40 * 41];   // labels pair-packed (stride 41, odd)
    __shared__ float sinp[40 * 41];    // inputs (stride 41, odd)
    __shared__ float smean[2];

    int bx = blockIdx.x;
    int half = bx & 1;
    int pwi  = bx >> 1;
    int pair = pwi / 80, w = pwi % 80;
    int n = pair >> 1, k0 = (pair & 1) * 2;
    int nk0 = n * 4 + k0;
    int h0 = half * 40;
    int tid = threadIdx.x;

    // means prologue: warp 0 reduces this pair's 80 plane-partials (before 1st sync)
    if (tid < 32) {
        float s0 = 0.f, si0 = 0.f, s1 = 0.f, si1 = 0.f;
        for (int j = tid; j < 80; j += 32) {
            float4 p = __ldg(&g_part2[pair * 80 + j]);
            s0 += p.x; si0 += p.y; s1 += p.z; si1 += p.w;
        }
        #pragma unroll
        for (int o = 16; o > 0; o >>= 1) {
            s0  += __shfl_down_sync(0xffffffffu, s0, o);
            si0 += __shfl_down_sync(0xffffffffu, si0, o);
            s1  += __shfl_down_sync(0xffffffffu, s1, o);
            si1 += __shfl_down_sync(0xffffffffu, si1, o);
        }
        if (tid == 0) {
            smean[0] = si0 / (s0 + 5.12f);   // 1e-5 * 512000
            smean[1] = si1 / (s1 + 5.12f);
        }
    }

    u64 taps[6]; mk_taps(taps);
    float num0 = 0.f, den0 = 0.f, num1 = 0.f, den1 = 0.f;
    float m0 = 0.f, m1 = 0.f;

    const u64*   base = g_bufA + (size_t)pair * VOX + (size_t)w * 80;
    const float* lb0  = labels + (size_t)nk0 * VOX + (size_t)w * 80;
    const float* lb1  = lb0 + VOX;
    const float* ib   = inputs + (size_t)n * VOX + (size_t)w * 80;

    for (int chunk = 0; chunk < 2; chunk++) {
        int cstart = chunk * 40;       // output d range [cstart, cstart+40)
        // zero pad cols: chunk0 -> j in [0,5) (d<0); chunk1 -> j in [45,50) (d>=80)
        for (int idx = tid; idx < 40 * 5; idx += 256) {
            int r = idx / 5, p = idx % 5;
            int j = (chunk == 0) ? p : 45 + p;
            spk[r * 51 + j] = 0ull;
        }
        // stage1: conv along H into smem; 225 threads = 45 d-cols x 5 h-segments of 8
        if (tid < 225) {
            int jv = tid % 45, hseg = tid / 45;
            int j  = (chunk == 0) ? jv + 5 : jv;      // smem col
            int dg = (chunk == 0) ? jv     : 35 + jv; // global d
            int r0 = hseg * 8;                        // local row start
            const u64* cp = base + dg;
            auto load = [&](int i) -> u64 {
                int hh = h0 + r0 - 5 + i;
                return (hh < 0 || hh >= 80) ? 0ull : __ldg(cp + (size_t)hh * 6400);
            };
            auto emit = [&](int o, u64 a) { spk[(r0 + o) * 51 + j] = a; };
            slide11p<8, 6>(taps, load, emit);
        }
        // stage labels (pair-packed) + inputs, coalesced along d
        for (int idx = tid; idx < 40 * 40; idx += 256) {
            int r = idx / 40, dl = idx % 40;
            size_t g = (size_t)(h0 + r) * 6400 + cstart + dl;
            int s = r * 41 + dl;
            slabp[s] = pack2(__ldg(lb0 + g), __ldg(lb1 + g));
            sinp[s]  = __ldg(ib + g);
        }
        __syncthreads();
        m0 = smean[0]; m1 = smean[1];
        // stage2: conv along D over spk + epilogue; 240 threads = 40 rows x 6 d-segs
        if (tid < 240) {
            int r = tid % 40, dseg = tid / 40;
            int d0 = (dseg < 4) ? dseg * 7 : 28 + (dseg - 4) * 6;
            auto load = [&](int i) -> u64 { return spk[r * 51 + d0 + i]; };
            auto emit = [&](int o, u64 a) {
                float2 c = unpack2(a);
                int s = r * 41 + d0 + o;
                float iv = sinp[s];
                float2 lv = unpack2(slabp[s]);
                float t0 = iv - m0; float q0 = t0 * t0; q0 *= q0;
                float t1 = iv - m1; float q1 = t1 * t1; q1 *= q1;
                float w0 = __expf(-q0);
                float w1 = __expf(-q1);
                float wc0 = w0 * c.x, wc1 = w1 * c.y;
                den0 += wc0; num0 += lv.x * wc0;
                den1 += wc1; num1 += lv.y * wc1;
            };
            if (dseg < 4) slide11<7>(taps, load, emit);
            else          slide11<6>(taps, load, emit);
        }
        __syncthreads();
    }

    // block reduce 4 accumulators
    #pragma unroll
    for (int o = 16; o > 0; o >>= 1) {
        num0 += __shfl_down_sync(0xffffffffu, num0, o);
        den0 += __shfl_down_sync(0xffffffffu, den0, o);
        num1 += __shfl_down_sync(0xffffffffu, num1, o);
        den1 += __shfl_down_sync(0xffffffffu, den1, o);
    }
    __shared__ float4 sacc[8];
    int wid = tid >> 5, lid = tid & 31;
    if (lid == 0) sacc[wid] = make_float4(num0, den0, num1, den1);
    __syncthreads();
    if (tid == 0) {
        float4 t = make_float4(0.f, 0.f, 0.f, 0.f);
        #pragma unroll
        for (int j = 0; j < 8; j++) {
            t.x += sacc[j].x; t.y += sacc[j].y;
            t.z += sacc[j].z; t.w += sacc[j].w;
        }
        g_partC[bx] = t;
    }
}

// ---------------- K final: ratio / loss ----------------
__global__ __launch_bounds__(256) void k_final(float* __restrict__ out) {
    int wid = threadIdx.x >> 5, lid = threadIdx.x & 31;   // wid = nk
    int n = wid >> 2, k = wid & 3;
    int pair = n * 2 + (k >> 1);
    int sel  = k & 1;
    __shared__ float sr[8];
    {
        float num = 0.f, den = 0.f;
        for (int j = lid; j < 160; j += 32) {
            float4 p = g_partC[pair * 160 + j];
            num += sel ? p.z : p.x;
            den += sel ? p.w : p.y;
        }
        #pragma unroll
        for (int o = 16; o > 0; o >>= 1) {
            num += __shfl_down_sync(0xffffffffu, num, o);
            den += __shfl_down_sync(0xffffffffu, den, o);
        }
        if (lid == 0) sr[wid] = fabsf(num / (den + 1e-6f));
    }
    __syncthreads();
    if (threadIdx.x == 0) {
        float loss = 0.f;
        #pragma unroll
        for (int k2 = 0; k2 < 4; k2++)
            loss += 0.5f * (sr[k2] + sr[4 + k2]);
        out[0] = 4.0f - loss;
    }
}

extern "C" void kernel_launch(void* const* d_in, const int* in_sizes, int n_in,
                              void* d_out, int out_size) {
    const float* labels = (const float*)d_in[0];
    const float* inputs = (const float*)d_in[1];
    if (n_in >= 2 && in_sizes[0] < in_sizes[1]) {
        const float* t = labels; labels = inputs; inputs = t;
    }
    float* out = (float*)d_out;

    kAB    <<<NPAIR * 80, 256>>>(labels, inputs);
    kB     <<<NPAIR * 80 * 2, 256>>>(labels, inputs);
    k_final<<<1, 256>>>(out);
}